// round 12
// baseline (speedup 1.0000x reference)
#include <cuda_runtime.h>

#define BB 128
#define SS 512
#define KK 4
#define DD 300
#define CC 20
#define NN 10000

// K1: 32 nodes/block; thread = (dc 0..4, pair 0..15, cg 0..3) -> 320 threads
#define DSPLIT 5
#define DCH (DD / DSPLIT)          // 60
#define P1_TPB 320
#define P1_NODES 32
#define P1_GRID ((NN + P1_NODES - 1) / P1_NODES)   // 313
#define P1_THREADS (P1_GRID * P1_TPB)              // 100160

// K2: grid (GCH, BB), 320 threads; thread = (s-group 0..63, quad 0..4)
#define GCH 8
#define SCH (SS / GCH)             // 64
#define G_TPB 320
#define G_GRP 64

#define EWN (BB * SS * KK)         // 262144

__device__ float g_P[NN * CC];           // P = node_emb @ fc_w^T (800 KB)
__device__ float g_EW[EWN];              // prefetched edge weights (1 MB)
__device__ float g_part[BB * GCH * CC];  // per-(b,chunk) logit partials
__device__ unsigned int g_done[BB];      // zero-init; self-resets each call

// ---------------------------------------------------------------------------
// K1: P-GEMM (pairs x 5 classes x 5 d-chunks, in-block split-D reduce)
// + overlapped random edge_w prefetch on otherwise-idle DRAM.
// ---------------------------------------------------------------------------
__global__ void __launch_bounds__(P1_TPB, 2) p_kernel(
    const float* __restrict__ node_emb, const float* __restrict__ fc_w,
    const int* __restrict__ EW, const float* __restrict__ edge_w)
{
    __shared__ float sF[DSPLIT * CC * DCH];          // 24 KB [dc][c][d]
    __shared__ float sAcc[DSPLIT][P1_NODES * CC];    // 12.8 KB

    const int t = threadIdx.x;

    for (int i = t; i < DSPLIT * CC * DCH; i += P1_TPB) {
        const int dc = i / (CC * DCH);
        const int r  = i % (CC * DCH);
        sF[i] = fc_w[(r / DCH) * DD + dc * DCH + (r % DCH)];
    }

    // Random edge_w prefetch: ~2.6 independent chains/thread, chip-wide MLP
    // ~262k; coalesced writes to g_EW consumed by K2 via stream order.
    for (int i = blockIdx.x * P1_TPB + t; i < EWN; i += P1_THREADS)
        g_EW[i] = __ldg(&edge_w[__ldg(&EW[i])]);

    __syncthreads();

    const int dc = t / 64;                 // 0..4
    const int w  = t % 64;
    const int pr = w >> 2;                 // 0..15 node-pair
    const int cg = w & 3;                  // 0..3  class-group (5 classes)
    const int n0 = blockIdx.x * P1_NODES + pr * 2;
    const int d0 = dc * DCH;

    if (n0 < NN) {                         // NN even -> pair never splits
        const float4* __restrict__ e0 = (const float4*)(node_emb + (size_t)n0 * DD + d0);
        const float4* __restrict__ e1 = (const float4*)(node_emb + (size_t)(n0 + 1) * DD + d0);
        const float4* __restrict__ f4 = (const float4*)(sF + dc * CC * DCH + cg * 5 * DCH);

        float a0[5] = {0.f, 0.f, 0.f, 0.f, 0.f};
        float a1[5] = {0.f, 0.f, 0.f, 0.f, 0.f};
        #pragma unroll
        for (int dq = 0; dq < DCH / 4; dq++) {       // 15 iters
            const float4 v0 = e0[dq];
            const float4 v1 = e1[dq];
            #pragma unroll
            for (int c5 = 0; c5 < 5; c5++) {
                const float4 fv = f4[c5 * (DCH / 4) + dq];
                a0[c5] += v0.x * fv.x + v0.y * fv.y + v0.z * fv.z + v0.w * fv.w;
                a1[c5] += v1.x * fv.x + v1.y * fv.y + v1.z * fv.z + v1.w * fv.w;
            }
        }
        #pragma unroll
        for (int c5 = 0; c5 < 5; c5++) {
            sAcc[dc][(pr * 2    ) * CC + cg * 5 + c5] = a0[c5];
            sAcc[dc][(pr * 2 + 1) * CC + cg * 5 + c5] = a1[c5];
        }
    }
    __syncthreads();

    const int base = blockIdx.x * P1_NODES * CC;
    for (int i = t; i < P1_NODES * CC; i += P1_TPB) {
        if (base + i < NN * CC) {
            float s = sAcc[0][i];
            #pragma unroll
            for (int d = 1; d < DSPLIT; d++) s += sAcc[d][i];
            g_P[base + i] = s;
        }
    }
}

// ---------------------------------------------------------------------------
// K2: 1024 blocks (occupancy-saturating). Thread = (s-group, class-quad),
// exactly one s-position each -> 5 independent float4 L2 gathers in flight.
// Last-arriving chunk block per b combines partials + softmax.
// ---------------------------------------------------------------------------
__global__ void __launch_bounds__(G_TPB) gather_kernel(
    const int* __restrict__ X, const int* __restrict__ NX,
    const float* __restrict__ node_w,
    const float* __restrict__ fc_b, float* __restrict__ out)
{
    __shared__ int   sX[SCH];
    __shared__ float sNW[SCH];
    __shared__ int   sNX[SCH * KK];
    __shared__ float sEW[SCH * KK];
    __shared__ float sred[G_GRP][CC];      // 5 KB

    const int ch = blockIdx.x;
    const int b  = blockIdx.y;
    const int s0 = ch * SCH;
    const int t  = threadIdx.x;

    // Coalesced staging (edge weights pre-resolved in g_EW by K1)
    if (t < SCH * KK) {
        sEW[t] = g_EW[(b * SS + s0) * KK + t];
        sNX[t] = NX[(b * SS + s0) * KK + t];
    } else if (t < SCH * KK + SCH) {
        const int i = t - SCH * KK;
        const int x = X[b * SS + s0 + i];
        sX[i]  = x;
        sNW[i] = __ldg(&node_w[x]);
    }
    __syncthreads();

    const int g = t / 5;                   // 0..63 s-group == s-position
    const int q = t % 5;                   // 0..4  class quad
    const float4* __restrict__ P4 = (const float4*)g_P;   // row stride 5

    {
        const int s = g;
        const float nw = sNW[s];
        float4 m = make_float4(0.f, 0.f, 0.f, 0.f);
        #pragma unroll
        for (int k = 0; k < KK; k++) {
            const float  ew = sEW[s * KK + k];
            const float4 p  = __ldg(&P4[sNX[s * KK + k] * 5 + q]);
            m.x += ew * p.x; m.y += ew * p.y; m.z += ew * p.z; m.w += ew * p.w;
        }
        const float4 r = __ldg(&P4[sX[s] * 5 + q]);
        const float inw = 1.f - nw;
        float4 acc;
        acc.x = inw * m.x + nw * r.x;
        acc.y = inw * m.y + nw * r.y;
        acc.z = inw * m.z + nw * r.z;
        acc.w = inw * m.w + nw * r.w;
        *(float4*)&sred[g][q * 4] = acc;
    }
    __syncthreads();

    // Fixed-order tree reduce over 64 s-groups -> deterministic
    #pragma unroll
    for (int off = G_GRP / 2; off > 0; off >>= 1) {
        if (t < off * 5) {
            const int gg = t / 5, qq = t % 5;
            float4 a = *(float4*)&sred[gg][qq * 4];
            float4 bb = *(float4*)&sred[gg + off][qq * 4];
            a.x += bb.x; a.y += bb.y; a.z += bb.z; a.w += bb.w;
            *(float4*)&sred[gg][qq * 4] = a;
        }
        __syncthreads();
    }

    if (t < CC) g_part[(b * GCH + ch) * CC + t] = sred[0][t];
    __syncthreads();

    if (t < 32) {
        unsigned last = 0;
        if (t == 0) {
            __threadfence();                               // release my partial
            last = (atomicAdd(&g_done[b], 1u) == GCH - 1) ? 1u : 0u;
        }
        last = __shfl_sync(0xffffffffu, last, 0);
        if (last) {
            if (t == 0) {
                g_done[b] = 0;                             // reset for replay
                __threadfence();                           // acquire partials
            }
            __syncwarp();
            float l = -1e30f;
            if (t < CC) {
                float s = fc_b[t];
                #pragma unroll
                for (int qch = 0; qch < GCH; qch++)
                    s += g_part[(b * GCH + qch) * CC + t];
                l = fmaxf(s, 0.f);
            }
            float mx = l;
            #pragma unroll
            for (int o = 16; o; o >>= 1) mx = fmaxf(mx, __shfl_xor_sync(0xffffffffu, mx, o));
            const float e = (t < CC) ? __expf(l - mx) : 0.f;
            float sum = e;
            #pragma unroll
            for (int o = 16; o; o >>= 1) sum += __shfl_xor_sync(0xffffffffu, sum, o);
            if (t < CC) out[b * CC + t] = e / sum;
        }
    }
}

// ---------------------------------------------------------------------------
extern "C" void kernel_launch(void* const* d_in, const int* in_sizes, int n_in,
                              void* d_out, int out_size)
{
    const int*   X        = (const int*)  d_in[0];
    const int*   NX       = (const int*)  d_in[1];
    const int*   EW       = (const int*)  d_in[2];
    const float* node_emb = (const float*)d_in[3];
    const float* edge_w   = (const float*)d_in[4];
    const float* node_w   = (const float*)d_in[5];
    const float* fc_w     = (const float*)d_in[6];
    const float* fc_b     = (const float*)d_in[7];
    float* out = (float*)d_out;

    p_kernel<<<P1_GRID, P1_TPB>>>(node_emb, fc_w, EW, edge_w);
    dim3 grid2(GCH, BB);
    gather_kernel<<<grid2, G_TPB>>>(X, NX, node_w, fc_b, out);
}